// round 2
// baseline (speedup 1.0000x reference)
#include <cuda_runtime.h>
#include <math.h>

#define CCH  32
#define HF   256
#define WF   256
#define MAXW 128
#define MBOX 1024

#define RROWS  44      // proven bound: rows <= 42
#define RMAXC  64      // proven bound: cols <= 63
#define RPITCH 65      // odd pitch -> conflict-friendly

__device__ int g_width[MBOX];
__device__ int g_order[MBOX];

// ---------------------------------------------------------------------------
// Kernel 1: widths (bit-identical discrete math) + stable descending rank.
// 128 blocks x 256 threads. Each block recomputes all widths into smem (cheap),
// then warp w ranks box i = blockIdx*8 + w via lane-parallel count + shuffle.
// ---------------------------------------------------------------------------
__global__ __launch_bounds__(256) void width_rank_kernel(
    const float* __restrict__ boxes, float* __restrict__ out_tail,
    int M, int write_tail)
{
    __shared__ int sw[MBOX];
    const int tid = threadIdx.x;

    for (int i = tid; i < MBOX; i += 256) {
        int w = -1;
        if (i < M) {
            const float* b = boxes + i * 8;
            float p1x = b[0]*0.25f, p1y = b[1]*0.25f;
            float p2x = b[2]*0.25f, p2y = b[3]*0.25f;
            float p4x = b[6]*0.25f, p4y = b[7]*0.25f;
            float dx2 = __fadd_rn(p2x,-p1x), dy2 = __fadd_rn(p2y,-p1y);
            float dx4 = __fadd_rn(p4x,-p1x), dy4 = __fadd_rn(p4y,-p1y);
            float bw = __fsqrt_rn(__fadd_rn(__fmul_rn(dx2,dx2), __fmul_rn(dy2,dy2)));
            float bh = __fsqrt_rn(__fadd_rn(__fmul_rn(dx4,dx4), __fmul_rn(dy4,dy4)));
            float bmaj = bw, bmin = bh;
            if (bw <= bh) { bmaj = bh; bmin = bw; }
            float ratio = __fdiv_rn(__fmul_rn(8.0f, bmaj), fmaxf(bmin, 1e-6f));
            w = (int)fminf(fmaxf(ceilf(ratio), 1.0f), 128.0f);
        }
        sw[i] = w;
    }
    __syncthreads();

    const int lane = tid & 31, wrp = tid >> 5;
    const int i = blockIdx.x * 8 + wrp;
    if (i < M) {
        const int w = sw[i];
        int rank = 0;
        #pragma unroll 4
        for (int t = 0; t < MBOX / 32; t++) {
            int j = t * 32 + lane;
            int wj = sw[j];
            rank += (wj > w) | ((wj == w) & (j < i));
        }
        #pragma unroll
        for (int o = 16; o; o >>= 1)
            rank += __shfl_xor_sync(0xffffffffu, rank, o);
        if (lane == 0) {
            g_order[rank] = i;
            g_width[i]    = w;
            if (write_tail) {
                out_tail[rank]     = (float)w;
                out_tail[M + rank] = (float)i;
            }
        }
    }
}

// ---------------------------------------------------------------------------
// Kernel 2: sampler.  Block = (sorted slot k, x-tile of 32 columns).
// Dense coalesced region fill into SMEM (per channel, with register prefetch
// of the next channel), LDS-based bilinear sampling, staged c-innermost
// float4 writeout.
// ---------------------------------------------------------------------------
__global__ __launch_bounds__(256) void sample_kernel(
    const float* __restrict__ fm,
    const float* __restrict__ boxes,
    const int*   __restrict__ mapping,
    float*       __restrict__ out)
{
    __shared__ float region[RROWS * RPITCH];   // 11440 B
    __shared__ float stage[256 * 33];          // 33792 B
    __shared__ float smn[8], smx[8], smny[8], smxy[8];

    const int bid  = blockIdx.x;
    const int k    = bid >> 2;
    const int tile = bid & 3;
    const int tid  = threadIdx.x;
    const int lane = tid & 31;
    const int wrp  = tid >> 5;
    const int y    = wrp;          // 0..7 output row
    const int xl   = lane;         // 0..31 within tile

    const int box   = g_order[k];
    const int width = g_width[box];
    const int xs    = tile << 5;

    float* const obase = out + ((size_t)k << 3) * 4096 + (size_t)xs * 32;
    // element (y, xl, c) lives at obase + y*4096 + xl*32 + c

    if (xs >= width) {
        const float4 z = make_float4(0.f, 0.f, 0.f, 0.f);
        #pragma unroll
        for (int j = 0; j < 8; j++) {
            int e  = (j * 256 + tid) << 2;          // tile-linear elem id
            int yy = e >> 10;
            int rr = e & 1023;                      // xl*32 + c
            *(float4*)(obase + (size_t)yy * 4096 + rr) = z;
        }
        return;
    }

    const int n = mapping[box];

    // geometry (same op sequence as the passing direct version)
    const float* b = boxes + box * 8;
    const float p1x = b[0]*0.25f, p1y = b[1]*0.25f;
    const float p2x = b[2]*0.25f, p2y = b[3]*0.25f;
    const float p4x = b[6]*0.25f, p4y = b[7]*0.25f;
    const float dx2 = __fadd_rn(p2x,-p1x), dy2 = __fadd_rn(p2y,-p1y);
    const float dx4 = __fadd_rn(p4x,-p1x), dy4 = __fadd_rn(p4y,-p1y);
    const float wff = (float)width;
    const float axx = __fdiv_rn(dx2, wff), axy = __fdiv_rn(dy2, wff);
    const float ayx = dx4 * 0.125f,        ayy = dy4 * 0.125f;

    const int  x   = xs + xl;
    const bool act = (x < width);
    const float fx = (float)x, fy = (float)y;
    const float sx = p1x + axx * fx + ayx * fy;
    const float sy = p1y + axy * fx + ayy * fy;

    // exact block-wide bbox of the active sample coords
    float mnx = act ? sx :  1e30f;
    float mxx = act ? sx : -1e30f;
    float mny = act ? sy :  1e30f;
    float mxy = act ? sy : -1e30f;
    #pragma unroll
    for (int o = 16; o; o >>= 1) {
        mnx = fminf(mnx, __shfl_xor_sync(0xffffffffu, mnx, o));
        mxx = fmaxf(mxx, __shfl_xor_sync(0xffffffffu, mxx, o));
        mny = fminf(mny, __shfl_xor_sync(0xffffffffu, mny, o));
        mxy = fmaxf(mxy, __shfl_xor_sync(0xffffffffu, mxy, o));
    }
    if (lane == 0) { smn[wrp]=mnx; smx[wrp]=mxx; smny[wrp]=mny; smxy[wrp]=mxy; }
    __syncthreads();
    float a0 = 1e30f, a1 = -1e30f, a2 = 1e30f, a3 = -1e30f;
    #pragma unroll
    for (int j = 0; j < 8; j++) {
        a0 = fminf(a0, smn[j]);  a1 = fmaxf(a1, smx[j]);
        a2 = fminf(a2, smny[j]); a3 = fmaxf(a3, smxy[j]);
    }
    const int rx0 = (int)floorf(a0);
    const int ry0 = (int)floorf(a2);
    const int cols = min(((int)floorf(a1) + 1) - rx0 + 1, RMAXC);
    const int rows = min(((int)floorf(a3) + 1) - ry0 + 1, RROWS);

    // per-thread bilinear setup (channel independent)
    const float x0f = floorf(sx), y0f = floorf(sy);
    const float tx = sx - x0f, ty = sy - y0f;
    const int x0 = (int)x0f, y0 = (int)y0f;
    const int x1 = x0 + 1,  y1 = y0 + 1;
    const bool vx0 = (x0 >= 0) & (x0 < WF);
    const bool vx1 = (x1 >= 0) & (x1 < WF);
    const bool vy0 = (y0 >= 0) & (y0 < HF);
    const bool vy1 = (y1 >= 0) & (y1 < HF);
    float w00 = (1.f - tx) * (1.f - ty); if (!(vx0 & vy0) || !act) w00 = 0.f;
    float w01 = tx * (1.f - ty);         if (!(vx1 & vy0) || !act) w01 = 0.f;
    float w10 = (1.f - tx) * ty;         if (!(vx0 & vy1) || !act) w10 = 0.f;
    float w11 = tx * ty;                 if (!(vx1 & vy1) || !act) w11 = 0.f;
    int ix = act ? (x0 - rx0) : 0;
    int iy = act ? (y0 - ry0) : 0;
    ix = min(max(ix, 0), RMAXC - 2);     // defensive (never triggers)
    iy = min(max(iy, 0), RROWS - 2);
    const int i00 = iy * RPITCH + ix;
    const int i10 = i00 + RPITCH;

    // channel loop with register-prefetched fills
    const float* const chbase0 = fm + (((size_t)n * CCH) << 16);
    float fbuf[12];

    // prefetch channel 0
    {
        const float* chb = chbase0;
        #pragma unroll
        for (int rr = 0; rr < 6; rr++) {
            int r  = wrp + rr * 8;
            int gy = min(max(ry0 + r, 0), HF - 1);
            const float* rowp = chb + (gy << 8);
            #pragma unroll
            for (int q = 0; q < 2; q++) {
                int cl = lane + q * 32;
                int gx = min(max(rx0 + cl, 0), WF - 1);
                if (r < rows && cl < cols) fbuf[rr * 2 + q] = __ldg(rowp + gx);
            }
        }
    }

    for (int c = 0; c < CCH; c++) {
        // commit prefetched channel c to SMEM
        #pragma unroll
        for (int rr = 0; rr < 6; rr++) {
            int r = wrp + rr * 8;
            #pragma unroll
            for (int q = 0; q < 2; q++) {
                int cl = lane + q * 32;
                if (r < rows && cl < cols) region[r * RPITCH + cl] = fbuf[rr * 2 + q];
            }
        }
        __syncthreads();

        // issue loads for channel c+1 (overlap with sampling below)
        if (c + 1 < CCH) {
            const float* chb = chbase0 + ((size_t)(c + 1) << 16);
            #pragma unroll
            for (int rr = 0; rr < 6; rr++) {
                int r  = wrp + rr * 8;
                int gy = min(max(ry0 + r, 0), HF - 1);
                const float* rowp = chb + (gy << 8);
                #pragma unroll
                for (int q = 0; q < 2; q++) {
                    int cl = lane + q * 32;
                    int gx = min(max(rx0 + cl, 0), WF - 1);
                    if (r < rows && cl < cols) fbuf[rr * 2 + q] = __ldg(rowp + gx);
                }
            }
        }

        // bilinear sample from SMEM
        float v = w00 * region[i00]     + w01 * region[i00 + 1]
                + w10 * region[i10]     + w11 * region[i10 + 1];
        stage[tid * 33 + c] = v;
        __syncthreads();
    }

    // coalesced writeout: 512B contiguous per warp
    #pragma unroll
    for (int j = 0; j < 8; j++) {
        int f  = j * 256 + tid;
        int e  = f << 2;                 // tile-linear elem id
        int yy = e >> 10;
        int xo = (e >> 5) & 31;
        int c  = e & 31;
        const float* sp = stage + (yy * 32 + xo) * 33 + c;
        float4 val = make_float4(sp[0], sp[1], sp[2], sp[3]);
        *(float4*)(obase + (size_t)yy * 4096 + xo * 32 + c) = val;
    }
}

// ---------------------------------------------------------------------------
extern "C" void kernel_launch(void* const* d_in, const int* in_sizes, int n_in,
                              void* d_out, int out_size) {
    const float* fm      = (const float*)d_in[0];
    const float* boxes   = (const float*)d_in[1];
    const int*   mapping = (const int*)  d_in[2];
    float*       out     = (float*)d_out;

    const int M = in_sizes[1] / 8;  // 1024
    const size_t main_elems = (size_t)M * 8 * MAXW * CCH;
    const int write_tail = ((size_t)out_size >= main_elems + 2 * (size_t)M) ? 1 : 0;

    width_rank_kernel<<<(M + 7) / 8, 256>>>(boxes, out + main_elems, M, write_tail);
    sample_kernel<<<M * 4, 256>>>(fm, boxes, mapping, out);
}

// round 3
// speedup vs baseline: 1.5245x; 1.5245x over previous
#include <cuda_runtime.h>
#include <math.h>

#define CCH  32
#define HF   256
#define WF   256
#define MAXW 128
#define MBOX 1024
#define IMG_WORDS (32u * 65536u)           // words per image (C*H*W)

// 134 MB transposed feature map scratch: layout (N, H, W, C), C contiguous.
__device__ float g_fmt[16u * IMG_WORDS];

__device__ float g_p1x[MBOX], g_p1y[MBOX];
__device__ float g_axx[MBOX], g_axy[MBOX];
__device__ float g_ayx[MBOX], g_ayy[MBOX];
__device__ int   g_width[MBOX];
__device__ int   g_order[MBOX];

// ---------------------------------------------------------------------------
// Kernel 1: transpose (N,C,H,W) -> (N,H,W,C).  Block = 64 spatial px x 32 ch.
// ---------------------------------------------------------------------------
__global__ __launch_bounds__(256) void transpose_kernel(const float* __restrict__ fm)
{
    __shared__ float tile[32][65];
    const int tid  = threadIdx.x;
    const int lane = tid & 31;
    const int wrp  = tid >> 5;

    const int px0 = blockIdx.x << 6;          // 64 px per block (linear over N*H*W)
    const int n   = px0 >> 16;
    const int pxi = px0 & 65535;
    const size_t ibase = (size_t)n * IMG_WORDS;

    // read: coalesced along W
    #pragma unroll
    for (int t = 0; t < 4; t++) {
        const int cc = wrp + t * 8;
        const float* src = fm + ibase + ((size_t)cc << 16) + pxi;
        tile[cc][lane]      = __ldg(src + lane);
        tile[cc][lane + 32] = __ldg(src + lane + 32);
    }
    __syncthreads();

    // write: coalesced along C
    float* dst = g_fmt + ibase + ((size_t)pxi << 5) + lane;
    #pragma unroll
    for (int t = 0; t < 8; t++) {
        const int xo = wrp + t * 8;
        dst[(size_t)xo << 5] = tile[lane][xo];
    }
}

// ---------------------------------------------------------------------------
// Kernel 2: widths (bit-identical discrete math), stable descending rank,
// and per-box sampling geometry.
// ---------------------------------------------------------------------------
__global__ __launch_bounds__(256) void width_rank_kernel(
    const float* __restrict__ boxes, float* __restrict__ out_tail,
    int M, int write_tail)
{
    __shared__ int sw[MBOX];
    const int tid = threadIdx.x;

    for (int i = tid; i < MBOX; i += 256) {
        int w = -1;
        if (i < M) {
            const float* b = boxes + i * 8;
            float p1x = b[0]*0.25f, p1y = b[1]*0.25f;
            float p2x = b[2]*0.25f, p2y = b[3]*0.25f;
            float p4x = b[6]*0.25f, p4y = b[7]*0.25f;
            float dx2 = __fadd_rn(p2x,-p1x), dy2 = __fadd_rn(p2y,-p1y);
            float dx4 = __fadd_rn(p4x,-p1x), dy4 = __fadd_rn(p4y,-p1y);
            float bw = __fsqrt_rn(__fadd_rn(__fmul_rn(dx2,dx2), __fmul_rn(dy2,dy2)));
            float bh = __fsqrt_rn(__fadd_rn(__fmul_rn(dx4,dx4), __fmul_rn(dy4,dy4)));
            float bmaj = bw, bmin = bh;
            if (bw <= bh) { bmaj = bh; bmin = bw; }
            float ratio = __fdiv_rn(__fmul_rn(8.0f, bmaj), fmaxf(bmin, 1e-6f));
            w = (int)fminf(fmaxf(ceilf(ratio), 1.0f), 128.0f);
        }
        sw[i] = w;
    }
    __syncthreads();

    const int lane = tid & 31, wrp = tid >> 5;
    const int i = blockIdx.x * 8 + wrp;
    if (i < M) {
        const int w = sw[i];
        int rank = 0;
        #pragma unroll 4
        for (int t = 0; t < MBOX / 32; t++) {
            int j = t * 32 + lane;
            int wj = sw[j];
            rank += (wj > w) | ((wj == w) & (j < i));
        }
        #pragma unroll
        for (int o = 16; o; o >>= 1)
            rank += __shfl_xor_sync(0xffffffffu, rank, o);
        if (lane == 0) {
            g_order[rank] = i;
            g_width[i]    = w;
            // geometry
            const float* b = boxes + i * 8;
            float p1x = b[0]*0.25f, p1y = b[1]*0.25f;
            float p2x = b[2]*0.25f, p2y = b[3]*0.25f;
            float p4x = b[6]*0.25f, p4y = b[7]*0.25f;
            float dx2 = __fadd_rn(p2x,-p1x), dy2 = __fadd_rn(p2y,-p1y);
            float dx4 = __fadd_rn(p4x,-p1x), dy4 = __fadd_rn(p4y,-p1y);
            float wf = (float)w;
            g_p1x[i] = p1x; g_p1y[i] = p1y;
            g_axx[i] = __fdiv_rn(dx2, wf);
            g_axy[i] = __fdiv_rn(dy2, wf);
            g_ayx[i] = dx4 * 0.125f;
            g_ayy[i] = dy4 * 0.125f;
            if (write_tail) {
                out_tail[rank]     = (float)w;
                out_tail[M + rank] = (float)i;
            }
        }
    }
}

// ---------------------------------------------------------------------------
// Kernel 3: sampler on transposed layout.  Warp = 8 consecutive x of one
// (slot k, row y); lane = channel.  Each tap is ONE 128B line; stores are
// natively coalesced.  Weights computed per lane-group, shfl-broadcast.
// ---------------------------------------------------------------------------
__global__ __launch_bounds__(256) void sample_kernel(
    const int*   __restrict__ mapping,
    float*       __restrict__ out)
{
    const int lane = threadIdx.x & 31;
    const int wg   = (blockIdx.x << 3) + (threadIdx.x >> 5);
    const int s0   = wg << 3;                 // first of 8 samples
    const int k    = s0 >> 10;
    const int y    = (s0 >> 7) & 7;
    const int xs   = s0 & 127;

    const int box   = g_order[k];
    const int width = g_width[box];

    float* const op = out + ((size_t)s0 << 5) + lane;   // out linear = s*32 + c

    if (xs >= width) {
        #pragma unroll
        for (int i = 0; i < 8; i++) op[(size_t)i << 5] = 0.f;
        return;
    }

    const int n = mapping[box];
    const float* const fb = g_fmt + ((size_t)n * IMG_WORDS) + lane;

    // per-lane geometry for sample i = lane & 7
    const float fx = (float)(xs + (lane & 7));
    const float fy = (float)y;
    const float sx = g_p1x[box] + g_axx[box] * fx + g_ayx[box] * fy;
    const float sy = g_p1y[box] + g_axy[box] * fx + g_ayy[box] * fy;
    const float x0f = floorf(sx), y0f = floorf(sy);
    const float tx = sx - x0f, ty = sy - y0f;
    const int x0 = (int)x0f, y0 = (int)y0f;
    const bool vx0 = ((unsigned)x0       < (unsigned)WF);
    const bool vx1 = ((unsigned)(x0 + 1) < (unsigned)WF);
    const bool vy0 = ((unsigned)y0       < (unsigned)HF);
    const bool vy1 = ((unsigned)(y0 + 1) < (unsigned)HF);
    float w00 = (1.f - tx) * (1.f - ty); if (!(vx0 & vy0)) w00 = 0.f;
    float w01 = tx * (1.f - ty);         if (!(vx1 & vy0)) w01 = 0.f;
    float w10 = (1.f - tx) * ty;         if (!(vx0 & vy1)) w10 = 0.f;
    float w11 = tx * ty;                 if (!(vx1 & vy1)) w11 = 0.f;
    const int xc0 = min(max(x0, 0), WF - 1);
    const int xc1 = min(max(x0 + 1, 0), WF - 1);
    const int yc0 = min(max(y0, 0), HF - 1);
    const int yc1 = min(max(y0 + 1, 0), HF - 1);
    const int o00 = (yc0 << 13) + (xc0 << 5);     // (yc0*256 + xc0)*32
    const int dxo = (xc1 - xc0) << 5;             // 0 or 32
    const int dyo = (yc1 - yc0) << 13;            // 0 or 8192

    #pragma unroll
    for (int i = 0; i < 8; i++) {
        const float W00 = __shfl_sync(0xffffffffu, w00, i);
        const float W01 = __shfl_sync(0xffffffffu, w01, i);
        const float W10 = __shfl_sync(0xffffffffu, w10, i);
        const float W11 = __shfl_sync(0xffffffffu, w11, i);
        const int   O00 = __shfl_sync(0xffffffffu, o00, i);
        const int   DX  = __shfl_sync(0xffffffffu, dxo, i);
        const int   DY  = __shfl_sync(0xffffffffu, dyo, i);
        float v = 0.f;
        if (xs + i < width) {
            const float* p = fb + O00;
            v = W00 * __ldg(p)
              + W01 * __ldg(p + DX)
              + W10 * __ldg(p + DY)
              + W11 * __ldg(p + DX + DY);
        }
        op[(size_t)i << 5] = v;
    }
}

// ---------------------------------------------------------------------------
extern "C" void kernel_launch(void* const* d_in, const int* in_sizes, int n_in,
                              void* d_out, int out_size) {
    const float* fm      = (const float*)d_in[0];
    const float* boxes   = (const float*)d_in[1];
    const int*   mapping = (const int*)  d_in[2];
    float*       out     = (float*)d_out;

    const int M = in_sizes[1] / 8;  // 1024
    const size_t main_elems = (size_t)M * 8 * MAXW * CCH;
    const int write_tail = ((size_t)out_size >= main_elems + 2 * (size_t)M) ? 1 : 0;

    const int fm_elems = in_sizes[0];                 // N*C*H*W
    const int tr_blocks = fm_elems / (CCH * 64);      // 64 px per block

    transpose_kernel<<<tr_blocks, 256>>>(fm);
    width_rank_kernel<<<(M + 7) / 8, 256>>>(boxes, out + main_elems, M, write_tail);
    sample_kernel<<<M * 16, 256>>>(mapping, out);
}